// round 14
// baseline (speedup 1.0000x reference)
#include <cuda_runtime.h>
#include <cuda_bf16.h>
#include <cstdint>
#include <math.h>

#define B_    16
#define N_    512
#define T_    96
#define FIN_  32
#define H_    128
#define FOUT_ 32

constexpr int       BN_TOT = B_ * N_;                       // 8192
constexpr long long M_TOT  = (long long)B_ * N_ * T_;       // 786432

using u64_t = unsigned long long;

// ---------------- pooled scratch (host .bss shadow must stay < 2 GiB) ----------------
//   [0, 201326592)            s1t_hi  (4b..5)    } overlapped by gi_hi (6..7)
//   [201326592, 402653184)    s1t_lo  (4b..5)    }
//   [402653184, 805306368)    h1 fp32 (3..4)     } overlapped by gi_lo (6..7) [603979776..1207959552)
//   [805306368, 1207959552)   Y0/S1 fp32 (2..4b) }
//   [0, 603979776)            gi_hi bf16 (6..7)
//   [603979776, 1207959552)   gi_lo bf16 (6..7)
//   [1207959552, 1409286144)  h2_hi (5..6)       } overlapped by gru_out (7..8)
//   [1409286144, 1610612736)  h2_lo (5..6)       }
//   [1207959552, 1610612736)  gru_out fp32 (7..8)
constexpr size_t POOL_BYTES = 1610612736ULL;   // 1.5 GiB
__device__ __align__(128) unsigned char g_pool[POOL_BYTES];

__device__ float g_adjn[N_ * N_];
__device__ __nv_bfloat16 g_adjn_hi[N_ * N_];
__device__ __nv_bfloat16 g_adjn_lo[N_ * N_];
__device__ float g_dis[N_];
__device__ __nv_bfloat16 g_wih_hi[3 * H_ * H_];
__device__ __nv_bfloat16 g_wih_lo[3 * H_ * H_];

// ---------------- f32x2 helpers ----------------
__device__ __forceinline__ u64_t bcast2(float x) {
    u64_t r; asm("mov.b64 %0, {%1,%2};" : "=l"(r) : "f"(x), "f"(x)); return r;
}
__device__ __forceinline__ u64_t lo2(const float4& v) {
    u64_t r; asm("mov.b64 %0, {%1,%2};" : "=l"(r) : "f"(v.x), "f"(v.y)); return r;
}
__device__ __forceinline__ u64_t hi2(const float4& v) {
    u64_t r; asm("mov.b64 %0, {%1,%2};" : "=l"(r) : "f"(v.z), "f"(v.w)); return r;
}
__device__ __forceinline__ void fma2(u64_t& d, u64_t a, u64_t b) {
    asm("fma.rn.f32x2 %0, %1, %2, %0;" : "+l"(d) : "l"(a), "l"(b));
}
__device__ __forceinline__ float2 unpack2(u64_t v) {
    float2 r; asm("mov.b64 {%0,%1}, %2;" : "=f"(r.x), "=f"(r.y) : "l"(v)); return r;
}

// ---------------- FMA-only activations (no MUFU) ----------------
__device__ __forceinline__ float frcp_fast(float d) {
    float r = __uint_as_float(0x7EF311C3u - __float_as_uint(d));
    r = r * (2.0f - d * r);
    r = r * (2.0f - d * r);
    return r;
}
__device__ __forceinline__ float tanh_fast(float x) {
    x = fminf(7.90531f, fmaxf(-7.90531f, x));
    float x2 = x * x;
    float p = -2.76076847742355e-16f;
    p = fmaf(p, x2, 2.00018790482477e-13f);
    p = fmaf(p, x2, -8.60467152213735e-11f);
    p = fmaf(p, x2, 5.12229709037114e-08f);
    p = fmaf(p, x2, 1.48572235717979e-05f);
    p = fmaf(p, x2, 6.37261928875436e-04f);
    p = fmaf(p, x2, 4.89352455891786e-03f);
    p = p * x;
    float q = 1.19825839466702e-06f;
    q = fmaf(q, x2, 1.18534705686654e-04f);
    q = fmaf(q, x2, 2.26843463243900e-03f);
    q = fmaf(q, x2, 4.89352518554385e-03f);
    return p * frcp_fast(q);
}
__device__ __forceinline__ float sigmoid_fast(float x) {
    return 0.5f + 0.5f * tanh_fast(0.5f * x);
}

// ---------------- mma.sync helpers ----------------
__device__ __forceinline__ uint32_t smem_u32(const void* p) {
    uint32_t a;
    asm("{ .reg .u64 t; cvta.to.shared.u64 t, %1; cvt.u32.u64 %0, t; }" : "=r"(a) : "l"(p));
    return a;
}
__device__ __forceinline__ void ldm_x4(uint32_t& r0, uint32_t& r1, uint32_t& r2, uint32_t& r3,
                                       uint32_t addr) {
    asm volatile("ldmatrix.sync.aligned.m8n8.x4.shared.b16 {%0,%1,%2,%3}, [%4];"
                 : "=r"(r0), "=r"(r1), "=r"(r2), "=r"(r3) : "r"(addr));
}
__device__ __forceinline__ void mma_bf16(float* c, const uint32_t* a, const uint32_t* b) {
    asm volatile("mma.sync.aligned.m16n8k16.row.col.f32.bf16.bf16.f32 "
                 "{%0,%1,%2,%3}, {%4,%5,%6,%7}, {%8,%9}, {%0,%1,%2,%3};"
                 : "+f"(c[0]), "+f"(c[1]), "+f"(c[2]), "+f"(c[3])
                 : "r"(a[0]), "r"(a[1]), "r"(a[2]), "r"(a[3]), "r"(b[0]), "r"(b[1]));
}
__device__ __forceinline__ void cp16(uint32_t dst, const void* src) {
    asm volatile("cp.async.ca.shared.global [%0], [%1], 16;" :: "r"(dst), "l"(src));
}
__device__ __forceinline__ void cp_commit() {
    asm volatile("cp.async.commit_group;" ::: "memory");
}
template <int NW>
__device__ __forceinline__ void cp_wait() {
    asm volatile("cp.async.wait_group %0;" :: "n"(NW) : "memory");
}
// XOR swizzle for [rows][128] bf16 arrays (256 B/row): byte offset
__device__ __forceinline__ int swz(int row, int col) {
    return row * 256 + ((((col >> 3) ^ (row & 7)) << 4) | ((col & 7) << 1));
}

// ---------------- adjacency normalization ----------------
__global__ void adj_rowsum_k(const float* __restrict__ adj, float* __restrict__ dis) {
    int i = threadIdx.x;
    float s = 1.0f;
    for (int j = 0; j < N_; j++) s += adj[i * N_ + j];
    dis[i] = (s > 0.0f) ? rsqrtf(s) : 0.0f;
}
__global__ void adj_norm_k(const float* __restrict__ adj, const float* __restrict__ dis,
                           float* __restrict__ out,
                           __nv_bfloat16* __restrict__ ohi, __nv_bfloat16* __restrict__ olo) {
    int j = blockIdx.x * blockDim.x + threadIdx.x;
    int i = blockIdx.y;
    float a = adj[i * N_ + j] + (i == j ? 1.0f : 0.0f);
    float v = dis[i] * a * dis[j];
    out[i * N_ + j] = v;
    __nv_bfloat16 h = __float2bfloat16(v);
    ohi[i * N_ + j] = h;
    olo[i * N_ + j] = __float2bfloat16(v - __bfloat162float(h));
}

// ---------------- elementwise fp32 -> bf16 hi/lo split ----------------
__global__ void split_k(const float* __restrict__ src, __nv_bfloat16* __restrict__ hi,
                        __nv_bfloat16* __restrict__ lo, int n) {
    int i = blockIdx.x * blockDim.x + threadIdx.x;
    if (i >= n) return;
    float v = src[i];
    __nv_bfloat16 h = __float2bfloat16(v);
    hi[i] = h;
    lo[i] = __float2bfloat16(v - __bfloat162float(h));
}

// ---------------- transpose + split ----------------
__global__ void transpose_split_k(const float* __restrict__ src,
                                  __nv_bfloat16* __restrict__ hi, __nv_bfloat16* __restrict__ lo) {
    __shared__ float tile[32][33];
    const int b = blockIdx.z;
    const long long cBase = (long long)blockIdx.x * 32;
    const long long nBase = (long long)blockIdx.y * 32;
    const float* s = src + (long long)b * N_ * (T_ * H_);
    #pragma unroll
    for (int i = threadIdx.y; i < 32; i += 8)
        tile[i][threadIdx.x] = s[(nBase + i) * (T_ * H_) + cBase + threadIdx.x];
    __syncthreads();
    const long long ob = (long long)b * (T_ * H_) * N_;
    #pragma unroll
    for (int i = threadIdx.y; i < 32; i += 8) {
        float v = tile[threadIdx.x][i];
        __nv_bfloat16 h = __float2bfloat16(v);
        long long o = ob + (cBase + i) * N_ + nBase + threadIdx.x;
        hi[o] = h;
        lo[o] = __float2bfloat16(v - __bfloat162float(h));
    }
}

// ---------------- tiled fp32 GEMM with FFMA2 (SIMT; steps 2,3,4, FC) ----------------
template <int BM, int BN, int BK, int TM, int TN, bool TRANSB, bool MASKB, bool RELU, bool BIAS>
__global__ void __launch_bounds__((BM / TM) * (BN / TN))
gemm_k(const float* __restrict__ A, const float* __restrict__ B,
       const float* __restrict__ bias, float* __restrict__ C,
       int M, int N, int K, long long sB, long long sC, int bias_mod) {
    constexpr int THREADS = (BM / TM) * (BN / TN);
    constexpr int MCH = TM / 4, NCH = TN / 4;
    constexpr int RS = BM / MCH, CS = BN / NCH;

    B += (long long)blockIdx.z * sB;
    C += (long long)blockIdx.z * sC;

    __shared__ float As[BK][BM + 4];
    __shared__ float Bs[BK][BN + 4];

    const int tid   = threadIdx.x;
    const int tcols = BN / TN;
    const int trow  = tid / tcols;
    const int tcol  = tid % tcols;
    const long long row0 = (long long)blockIdx.y * BM;
    const int col0 = blockIdx.x * BN;

    u64_t acc[TM][TN / 2];
    #pragma unroll
    for (int m = 0; m < TM; m++)
        #pragma unroll
        for (int p = 0; p < TN / 2; p++) acc[m][p] = 0ULL;

    for (int k0 = 0; k0 < K; k0 += BK) {
        #pragma unroll
        for (int i = tid; i < BM * BK / 4; i += THREADS) {
            int r = i / (BK / 4), kk = (i % (BK / 4)) * 4;
            float4 v = *(const float4*)&A[(row0 + r) * K + k0 + kk];
            As[kk + 0][r] = v.x; As[kk + 1][r] = v.y;
            As[kk + 2][r] = v.z; As[kk + 3][r] = v.w;
        }
        if (!TRANSB) {
            #pragma unroll
            for (int i = tid; i < BK * BN / 4; i += THREADS) {
                int r = i / (BN / 4), c = (i % (BN / 4)) * 4;
                float4 v = *(const float4*)&B[(long long)(k0 + r) * N + col0 + c];
                if (MASKB) {
                    if (v.x == -1.0f) v.x = 0.0f;
                    if (v.y == -1.0f) v.y = 0.0f;
                    if (v.z == -1.0f) v.z = 0.0f;
                    if (v.w == -1.0f) v.w = 0.0f;
                }
                *(float4*)&Bs[r][c] = v;
            }
        } else {
            #pragma unroll
            for (int i = tid; i < BN * BK / 4; i += THREADS) {
                int c = i / (BK / 4), kk = (i % (BK / 4)) * 4;
                float4 v = *(const float4*)&B[(long long)(col0 + c) * K + k0 + kk];
                Bs[kk + 0][c] = v.x; Bs[kk + 1][c] = v.y;
                Bs[kk + 2][c] = v.z; Bs[kk + 3][c] = v.w;
            }
        }
        __syncthreads();

        #pragma unroll 4
        for (int k = 0; k < BK; k++) {
            u64_t av[TM];
            #pragma unroll
            for (int i = 0; i < MCH; i++) {
                float4 a = *(const float4*)&As[k][i * RS + trow * 4];
                av[i * 4 + 0] = bcast2(a.x); av[i * 4 + 1] = bcast2(a.y);
                av[i * 4 + 2] = bcast2(a.z); av[i * 4 + 3] = bcast2(a.w);
            }
            u64_t bp[TN / 2];
            #pragma unroll
            for (int j = 0; j < NCH; j++) {
                float4 b = *(const float4*)&Bs[k][j * CS + tcol * 4];
                bp[j * 2 + 0] = lo2(b);
                bp[j * 2 + 1] = hi2(b);
            }
            #pragma unroll
            for (int m = 0; m < TM; m++)
                #pragma unroll
                for (int p = 0; p < TN / 2; p++)
                    fma2(acc[m][p], av[m], bp[p]);
        }
        __syncthreads();
    }

    #pragma unroll
    for (int i = 0; i < MCH; i++) {
        #pragma unroll
        for (int mm = 0; mm < 4; mm++) {
            long long row = row0 + i * RS + trow * 4 + mm;
            int m = i * 4 + mm;
            #pragma unroll
            for (int j = 0; j < NCH; j++) {
                int col = col0 + j * CS + tcol * 4;
                float2 lo = unpack2(acc[m][j * 2]);
                float2 hi = unpack2(acc[m][j * 2 + 1]);
                float4 v = make_float4(lo.x, lo.y, hi.x, hi.y);
                if (BIAS) {
                    int cb = col % bias_mod;
                    v.x += bias[cb]; v.y += bias[cb + 1];
                    v.z += bias[cb + 2]; v.w += bias[cb + 3];
                }
                if (RELU) {
                    v.x = fmaxf(v.x, 0.f); v.y = fmaxf(v.y, 0.f);
                    v.z = fmaxf(v.z, 0.f); v.w = fmaxf(v.w, 0.f);
                }
                *(float4*)&C[row * N + col] = v;
            }
        }
    }
}

// ---------------- split-bf16 tensor-core GEMM (mma.sync, cp.async 2-stage) ----------------
// Always writes split bf16 hi/lo output; RELU_OUT applies relu before the split.
constexpr int MMA_ARR  = 128 * 40;
constexpr int MMA_STAGE = 4 * MMA_ARR;
constexpr int MMA_SMEM = 2 * MMA_STAGE * 2;        // 81920 bytes

template <bool RELU_OUT>
__global__ void __launch_bounds__(256, 2)
mma_gemm_k(const __nv_bfloat16* __restrict__ Ahi, const __nv_bfloat16* __restrict__ Alo,
           long long lda,
           const __nv_bfloat16* __restrict__ Bhi, const __nv_bfloat16* __restrict__ Blo,
           long long ldb, long long bzRows,
           const float* __restrict__ bias, int bias_mod,
           __nv_bfloat16* __restrict__ DhiOut, __nv_bfloat16* __restrict__ DloOut,
           long long ldd, long long dz, int K) {
    extern __shared__ __align__(16) __nv_bfloat16 smem[];

    const int tid = threadIdx.x, wid = tid >> 5, lane = tid & 31;
    const int wm = wid >> 1, wn = wid & 1;
    const long long z = blockIdx.z;
    const long long aRow0 = (long long)blockIdx.y * 128;
    const long long bRow0 = (long long)blockIdx.x * 128 + z * bzRows;

    const __nv_bfloat16* srcs[4] = {Ahi + aRow0 * lda, Alo + aRow0 * lda,
                                    Bhi + bRow0 * ldb, Blo + bRow0 * ldb};
    const long long lds[4] = {lda, lda, ldb, ldb};

    const int e0 = tid, e1 = tid + 256;
    const int r0c = e0 >> 2, q0c = e0 & 3;
    const int r1c = e1 >> 2, q1c = e1 & 3;

    auto load_stage = [&](int stage, int kc) {
        #pragma unroll
        for (int arr = 0; arr < 4; arr++) {
            __nv_bfloat16* dst = smem + stage * MMA_STAGE + arr * MMA_ARR;
            cp16(smem_u32(dst + r0c * 40 + q0c * 8),
                 srcs[arr] + (long long)r0c * lds[arr] + kc + q0c * 8);
            cp16(smem_u32(dst + r1c * 40 + q1c * 8),
                 srcs[arr] + (long long)r1c * lds[arr] + kc + q1c * 8);
        }
        cp_commit();
    };

    float acc[2][8][4];
    #pragma unroll
    for (int mf = 0; mf < 2; mf++)
        #pragma unroll
        for (int nf = 0; nf < 8; nf++)
            #pragma unroll
            for (int q = 0; q < 4; q++) acc[mf][nf][q] = 0.0f;

    // A fragment lanes (canonical x4)
    const int a_r  = lane & 15;
    const int a_c8 = (lane >> 4) << 3;
    // B fragment lanes for x4 (validated in gru_mma_k): lanes 0-7 n0-7@k0,
    // 8-15 n0-7@k8, 16-23 n8-15@k0, 24-31 n8-15@k8
    const int b_rowadd = ((lane >> 4) << 3) + (lane & 7);
    const int b_kadd   = ((lane >> 3) & 1) << 3;

    const int nk = K >> 5;
    load_stage(0, 0);

    for (int i = 0; i < nk; i++) {
        const int stage = i & 1;
        if (i + 1 < nk) {
            load_stage(stage ^ 1, (i + 1) << 5);
            cp_wait<1>();
        } else {
            cp_wait<0>();
        }
        __syncthreads();

        const __nv_bfloat16* sAhi = smem + stage * MMA_STAGE + 0 * MMA_ARR;
        const __nv_bfloat16* sAlo = smem + stage * MMA_STAGE + 1 * MMA_ARR;
        const __nv_bfloat16* sBhi = smem + stage * MMA_STAGE + 2 * MMA_ARR;
        const __nv_bfloat16* sBlo = smem + stage * MMA_STAGE + 3 * MMA_ARR;

        #pragma unroll
        for (int ks = 0; ks < 2; ks++) {
            const int kk = ks * 16;
            uint32_t ahi[2][4], alo[2][4];
            #pragma unroll
            for (int mf = 0; mf < 2; mf++) {
                int row = wm * 32 + mf * 16 + a_r;
                ldm_x4(ahi[mf][0], ahi[mf][1], ahi[mf][2], ahi[mf][3],
                       smem_u32(sAhi + row * 40 + kk + a_c8));
                ldm_x4(alo[mf][0], alo[mf][1], alo[mf][2], alo[mf][3],
                       smem_u32(sAlo + row * 40 + kk + a_c8));
            }
            #pragma unroll
            for (int pf = 0; pf < 4; pf++) {
                int nrow = wn * 64 + pf * 16 + b_rowadd;
                uint32_t bh4[4], bl4[4];
                ldm_x4(bh4[0], bh4[1], bh4[2], bh4[3],
                       smem_u32(sBhi + nrow * 40 + kk + b_kadd));
                ldm_x4(bl4[0], bl4[1], bl4[2], bl4[3],
                       smem_u32(sBlo + nrow * 40 + kk + b_kadd));
                #pragma unroll
                for (int q = 0; q < 2; q++) {
                    int nf = pf * 2 + q;
                    uint32_t bh2[2] = {bh4[q * 2], bh4[q * 2 + 1]};
                    uint32_t bl2[2] = {bl4[q * 2], bl4[q * 2 + 1]};
                    #pragma unroll
                    for (int mf = 0; mf < 2; mf++) {
                        mma_bf16(acc[mf][nf], ahi[mf], bh2);
                        mma_bf16(acc[mf][nf], ahi[mf], bl2);
                        mma_bf16(acc[mf][nf], alo[mf], bh2);
                    }
                }
            }
        }
        __syncthreads();
    }

    const int colBlk = blockIdx.x * 128;
    #pragma unroll
    for (int mf = 0; mf < 2; mf++) {
        #pragma unroll
        for (int nf = 0; nf < 8; nf++) {
            int col = colBlk + wn * 64 + nf * 8 + (lane & 3) * 2;
            int cb = col % bias_mod;
            float bb0 = bias[cb], bb1 = bias[cb + 1];
            long long r0 = aRow0 + wm * 32 + mf * 16 + (lane >> 2);
            #pragma unroll
            for (int h = 0; h < 2; h++) {
                long long row = r0 + h * 8;
                float v0 = acc[mf][nf][h * 2 + 0] + bb0;
                float v1 = acc[mf][nf][h * 2 + 1] + bb1;
                if (RELU_OUT) { v0 = fmaxf(v0, 0.0f); v1 = fmaxf(v1, 0.0f); }
                long long o = z * dz + row * ldd + col;
                __nv_bfloat16 h0 = __float2bfloat16(v0);
                __nv_bfloat16 h1 = __float2bfloat16(v1);
                __nv_bfloat162 hv; hv.x = h0; hv.y = h1;
                __nv_bfloat162 lv;
                lv.x = __float2bfloat16(v0 - __bfloat162float(h0));
                lv.y = __float2bfloat16(v1 - __bfloat162float(h1));
                *(__nv_bfloat162*)(DhiOut + o) = hv;
                *(__nv_bfloat162*)(DloOut + o) = lv;
            }
        }
    }
}

// ---------------- fused persistent GRU with tensor-core recurrence ----------------
constexpr int GRU_SMEM = 229376;

__global__ void __launch_bounds__(256, 1)
gru_mma_k(const __nv_bfloat16* __restrict__ gi_hi, const __nv_bfloat16* __restrict__ gi_lo,
          const float* __restrict__ w_hh,
          const float* __restrict__ b_hh, float* __restrict__ out) {
    extern __shared__ __align__(16) char gsm[];
    char* whh_hi = gsm;                  // 98304 B
    char* whh_lo = gsm + 98304;          // 98304 B
    char* h_hi   = gsm + 196608;         // 16384 B
    char* h_lo   = gsm + 212992;         // 16384 B

    const int tid = threadIdx.x, wid = tid >> 5, lane = tid & 31;
    const int wm = wid >> 2, wn = wid & 3;
    const long long bn0 = (long long)blockIdx.x * 64;

    for (int i = tid; i < 384 * 128; i += 256) {
        int n = i >> 7, c = i & 127;
        float v = w_hh[i];
        __nv_bfloat16 hh = __float2bfloat16(v);
        int off = swz(n, c);
        *(__nv_bfloat16*)(whh_hi + off) = hh;
        *(__nv_bfloat16*)(whh_lo + off) = __float2bfloat16(v - __bfloat162float(hh));
    }
    for (int i = tid * 4; i < 16384; i += 1024) {
        *(uint32_t*)(h_hi + i) = 0;
        *(uint32_t*)(h_lo + i) = 0;
    }

    float bh[3][4][2];
    #pragma unroll
    for (int g = 0; g < 3; g++)
        #pragma unroll
        for (int nf = 0; nf < 4; nf++) {
            int c = g * 128 + wn * 32 + nf * 8 + (lane & 3) * 2;
            bh[g][nf][0] = b_hh[c];
            bh[g][nf][1] = b_hh[c + 1];
        }

    float hreg[2][4][2][2];
    #pragma unroll
    for (int mf = 0; mf < 2; mf++)
        #pragma unroll
        for (int nf = 0; nf < 4; nf++) {
            hreg[mf][nf][0][0] = 0.f; hreg[mf][nf][0][1] = 0.f;
            hreg[mf][nf][1][0] = 0.f; hreg[mf][nf][1][1] = 0.f;
        }
    __syncthreads();

    const int a_r = lane & 15, a_c8 = (lane >> 4) << 3;
    const int b_g = lane >> 3, b_ln = lane & 7;
    const int b_rowadd = ((b_g >> 1) << 3) + b_ln;
    const int b_kadd = (b_g & 1) << 3;

    for (int t = 0; t < T_; t++) {
        float acc[2][3][4][4];
        #pragma unroll
        for (int mf = 0; mf < 2; mf++)
            #pragma unroll
            for (int g = 0; g < 3; g++)
                #pragma unroll
                for (int nf = 0; nf < 4; nf++) {
                    acc[mf][g][nf][0] = 0.f; acc[mf][g][nf][1] = 0.f;
                    acc[mf][g][nf][2] = 0.f; acc[mf][g][nf][3] = 0.f;
                }

        #pragma unroll 1
        for (int ks = 0; ks < 8; ks++) {
            const int kk = ks * 16;
            uint32_t ahi[2][4], alo[2][4];
            #pragma unroll
            for (int mf = 0; mf < 2; mf++) {
                int row = wm * 32 + mf * 16 + a_r;
                ldm_x4(ahi[mf][0], ahi[mf][1], ahi[mf][2], ahi[mf][3],
                       smem_u32(h_hi + swz(row, kk + a_c8)));
                ldm_x4(alo[mf][0], alo[mf][1], alo[mf][2], alo[mf][3],
                       smem_u32(h_lo + swz(row, kk + a_c8)));
            }
            #pragma unroll
            for (int g = 0; g < 3; g++) {
                #pragma unroll
                for (int p = 0; p < 2; p++) {
                    int rowb = g * 128 + wn * 32 + p * 16 + b_rowadd;
                    int kcol = kk + b_kadd;
                    uint32_t bhr[4], blr[4];
                    ldm_x4(bhr[0], bhr[1], bhr[2], bhr[3],
                           smem_u32(whh_hi + swz(rowb, kcol)));
                    ldm_x4(blr[0], blr[1], blr[2], blr[3],
                           smem_u32(whh_lo + swz(rowb, kcol)));
                    #pragma unroll
                    for (int q = 0; q < 2; q++) {
                        int nf = p * 2 + q;
                        uint32_t bh2[2] = {bhr[q * 2], bhr[q * 2 + 1]};
                        uint32_t bl2[2] = {blr[q * 2], blr[q * 2 + 1]};
                        #pragma unroll
                        for (int mf = 0; mf < 2; mf++) {
                            mma_bf16(acc[mf][g][nf], ahi[mf], bh2);
                            mma_bf16(acc[mf][g][nf], ahi[mf], bl2);
                            mma_bf16(acc[mf][g][nf], alo[mf], bh2);
                        }
                    }
                }
            }
        }
        __syncthreads();

        #pragma unroll
        for (int mf = 0; mf < 2; mf++) {
            #pragma unroll
            for (int nf = 0; nf < 4; nf++) {
                #pragma unroll
                for (int hh = 0; hh < 2; hh++) {
                    int m = wm * 32 + mf * 16 + (lane >> 2) + hh * 8;
                    long long rg = bn0 + m;
                    int c = wn * 32 + nf * 8 + (lane & 3) * 2;
                    long long gio = (rg * T_ + t) * 384 + c;
                    __nv_bfloat162 xrh = *(const __nv_bfloat162*)(gi_hi + gio);
                    __nv_bfloat162 xrl = *(const __nv_bfloat162*)(gi_lo + gio);
                    __nv_bfloat162 xzh = *(const __nv_bfloat162*)(gi_hi + gio + 128);
                    __nv_bfloat162 xzl = *(const __nv_bfloat162*)(gi_lo + gio + 128);
                    __nv_bfloat162 xnh = *(const __nv_bfloat162*)(gi_hi + gio + 256);
                    __nv_bfloat162 xnl = *(const __nv_bfloat162*)(gi_lo + gio + 256);
                    float xr0 = __bfloat162float(xrh.x) + __bfloat162float(xrl.x);
                    float xr1 = __bfloat162float(xrh.y) + __bfloat162float(xrl.y);
                    float xz0 = __bfloat162float(xzh.x) + __bfloat162float(xzl.x);
                    float xz1 = __bfloat162float(xzh.y) + __bfloat162float(xzl.y);
                    float xn0 = __bfloat162float(xnh.x) + __bfloat162float(xnl.x);
                    float xn1 = __bfloat162float(xnh.y) + __bfloat162float(xnl.y);
                    float rr0 = sigmoid_fast(xr0 + acc[mf][0][nf][hh * 2]     + bh[0][nf][0]);
                    float rr1 = sigmoid_fast(xr1 + acc[mf][0][nf][hh * 2 + 1] + bh[0][nf][1]);
                    float zz0 = sigmoid_fast(xz0 + acc[mf][1][nf][hh * 2]     + bh[1][nf][0]);
                    float zz1 = sigmoid_fast(xz1 + acc[mf][1][nf][hh * 2 + 1] + bh[1][nf][1]);
                    float nn0 = tanh_fast(xn0 + rr0 * (acc[mf][2][nf][hh * 2]     + bh[2][nf][0]));
                    float nn1 = tanh_fast(xn1 + rr1 * (acc[mf][2][nf][hh * 2 + 1] + bh[2][nf][1]));
                    float hp0 = hreg[mf][nf][hh][0], hp1 = hreg[mf][nf][hh][1];
                    float h0 = fmaf(zz0, hp0 - nn0, nn0);
                    float h1 = fmaf(zz1, hp1 - nn1, nn1);
                    hreg[mf][nf][hh][0] = h0; hreg[mf][nf][hh][1] = h1;

                    float2 o; o.x = h0; o.y = h1;
                    *(float2*)(out + (rg * T_ + t) * 128 + c) = o;

                    __nv_bfloat16 c0 = __float2bfloat16(h0);
                    __nv_bfloat16 c1 = __float2bfloat16(h1);
                    __nv_bfloat162 hv; hv.x = c0; hv.y = c1;
                    __nv_bfloat162 lv;
                    lv.x = __float2bfloat16(h0 - __bfloat162float(c0));
                    lv.y = __float2bfloat16(h1 - __bfloat162float(c1));
                    int off = swz(m, c);
                    *(__nv_bfloat162*)(h_hi + off) = hv;
                    *(__nv_bfloat162*)(h_lo + off) = lv;
                }
            }
        }
        __syncthreads();
    }
}

// ---------------- launch ----------------
extern "C" void kernel_launch(void* const* d_in, const int* in_sizes, int n_in,
                              void* d_out, int out_size) {
    const float* x     = (const float*)d_in[0];
    const float* adj   = (const float*)d_in[1];
    const float* gc_w0 = (const float*)d_in[2];
    const float* gc_b0 = (const float*)d_in[3];
    const float* gc_w1 = (const float*)d_in[4];
    const float* gc_b1 = (const float*)d_in[5];
    const float* w_ih  = (const float*)d_in[6];
    const float* w_hh  = (const float*)d_in[7];
    const float* b_ih  = (const float*)d_in[8];
    const float* b_hh  = (const float*)d_in[9];
    const float* w_fc  = (const float*)d_in[10];
    const float* b_fc  = (const float*)d_in[11];
    float* out = (float*)d_out;

    unsigned char* pool;
    float *adjn, *dis;
    __nv_bfloat16 *adjn_hi, *adjn_lo, *wih_hi, *wih_lo;
    cudaGetSymbolAddress((void**)&pool,    g_pool);
    cudaGetSymbolAddress((void**)&adjn,    g_adjn);
    cudaGetSymbolAddress((void**)&adjn_hi, g_adjn_hi);
    cudaGetSymbolAddress((void**)&adjn_lo, g_adjn_lo);
    cudaGetSymbolAddress((void**)&dis,     g_dis);
    cudaGetSymbolAddress((void**)&wih_hi,  g_wih_hi);
    cudaGetSymbolAddress((void**)&wih_lo,  g_wih_lo);

    __nv_bfloat16* s1t_hi = (__nv_bfloat16*)(pool + 0);
    __nv_bfloat16* s1t_lo = (__nv_bfloat16*)(pool + 201326592ULL);
    float*         h1     = (float*)(pool + 402653184ULL);
    float*         s1     = (float*)(pool + 805306368ULL);   // also Y0
    __nv_bfloat16* gi_hi  = (__nv_bfloat16*)(pool + 0);
    __nv_bfloat16* gi_lo  = (__nv_bfloat16*)(pool + 603979776ULL);
    __nv_bfloat16* h2_hi  = (__nv_bfloat16*)(pool + 1207959552ULL);
    __nv_bfloat16* h2_lo  = (__nv_bfloat16*)(pool + 1409286144ULL);
    float*         gru_o  = (float*)(pool + 1207959552ULL);

    const int M = (int)M_TOT;   // 786432

    // 1) adjacency normalization (+ bf16 split) and w_ih split
    adj_rowsum_k<<<1, N_>>>(adj, dis);
    adj_norm_k<<<dim3(N_ / 256, N_), 256>>>(adj, dis, adjn, adjn_hi, adjn_lo);
    split_k<<<(3 * H_ * H_ + 255) / 256, 256>>>(w_ih, wih_hi, wih_lo, 3 * H_ * H_);

    // 2) A-hop on raw (masked) x: Y0 = adjn @ mask(x)   (SIMT)
    gemm_k<128, 128, 16, 8, 8, false, true, false, false>
        <<<dim3((T_ * FIN_) / 128, N_ / 128, B_), 256>>>(
            adjn, x, nullptr, s1 /*Y0*/, N_, T_ * FIN_, N_,
            (long long)N_ * T_ * FIN_, (long long)N_ * T_ * FIN_, 1);

    // 3) h1 = relu(Y0 @ gc_w0 + b0)  (SIMT)
    gemm_k<128, 128, 16, 8, 8, false, false, true, true>
        <<<dim3(1, M / 128), 256>>>(s1 /*Y0*/, gc_w0, gc_b0, h1,
                                    M, H_, FIN_, 0, 0, H_);

    // 4) S1 = h1 @ gc_w1  (SIMT, fp32)
    gemm_k<128, 128, 16, 8, 8, false, false, false, false>
        <<<dim3(1, M / 128), 256>>>(h1, gc_w1, nullptr, s1,
                                    M, H_, H_, 0, 0, 1);

    // 4b) transpose + split: S1 -> S1T bf16 hi/lo
    transpose_split_k<<<dim3((T_ * H_) / 32, N_ / 32, B_), dim3(32, 8)>>>(s1, s1t_hi, s1t_lo);

    // 5) h2 = relu(adjn @ S1 + b1)  (mma.sync; split-out h2)
    cudaFuncSetAttribute(mma_gemm_k<true>,  cudaFuncAttributeMaxDynamicSharedMemorySize, MMA_SMEM);
    cudaFuncSetAttribute(mma_gemm_k<false>, cudaFuncAttributeMaxDynamicSharedMemorySize, MMA_SMEM);
    mma_gemm_k<true><<<dim3((T_ * H_) / 128, N_ / 128, B_), 256, MMA_SMEM>>>(
        adjn_hi, adjn_lo, N_,
        s1t_hi, s1t_lo, N_, (long long)T_ * H_,
        gc_b1, H_,
        h2_hi, h2_lo,
        (long long)T_ * H_, (long long)N_ * T_ * H_, N_);

    // 6) GI = h2 @ w_ih^T + b_ih  (mma.sync; split-out gi, no relu)
    mma_gemm_k<false><<<dim3((3 * H_) / 128, M / 128, 1), 256, MMA_SMEM>>>(
        h2_hi, h2_lo, H_,
        wih_hi, wih_lo, H_, 0,
        b_ih, 3 * H_,
        gi_hi, gi_lo,
        3 * H_, 0, H_);

    // 7) fused GRU recurrence, tensor-core gh (single persistent launch)
    cudaFuncSetAttribute(gru_mma_k, cudaFuncAttributeMaxDynamicSharedMemorySize, GRU_SMEM);
    gru_mma_k<<<BN_TOT / 64, 256, GRU_SMEM>>>(gi_hi, gi_lo, w_hh, b_hh, gru_o);

    // 8) FC: out = gru_out @ w_fc + b_fc  (SIMT)
    gemm_k<128, 32, 16, 8, 4, false, false, false, true>
        <<<dim3(1, M / 128), 128>>>(gru_o, w_fc, b_fc, out,
                                    M, FOUT_, H_, 0, 0, FOUT_);
}

// round 16
// speedup vs baseline: 1.1073x; 1.1073x over previous
#include <cuda_runtime.h>
#include <cuda_bf16.h>
#include <cstdint>
#include <math.h>

#define B_    16
#define N_    512
#define T_    96
#define FIN_  32
#define H_    128
#define FOUT_ 32

constexpr int       BN_TOT = B_ * N_;                       // 8192
constexpr long long M_TOT  = (long long)B_ * N_ * T_;       // 786432

using u64_t = unsigned long long;

// ---------------- pooled scratch (host .bss shadow must stay < 2 GiB) ----------------
//   [0, 201326592)            xt_hi (pre..2) ; s1t_hi (4b..5) ; gi [0,1207959552) (6..7)
//   [201326592, 402653184)    xt_lo ; s1t_lo
//   [402653184, 603979776)    h1_hi bf16 (3..4)
//   [603979776, 805306368)    h1_lo bf16 (3..4)
//   [805306368, 1207959552)   Y0/S1 fp32 (2..4b)
//   [1207959552, 1409286144)  h2_hi (5..6)   } overlapped by gru_out (7..8)
//   [1409286144, 1610612736)  h2_lo (5..6)   }
constexpr size_t POOL_BYTES = 1610612736ULL;   // 1.5 GiB
__device__ __align__(128) unsigned char g_pool[POOL_BYTES];

__device__ float g_adjn[N_ * N_];
__device__ __nv_bfloat16 g_adjn_hi[N_ * N_];
__device__ __nv_bfloat16 g_adjn_lo[N_ * N_];
__device__ float g_dis[N_];
__device__ __nv_bfloat16 g_wih_hi[3 * H_ * H_];
__device__ __nv_bfloat16 g_wih_lo[3 * H_ * H_];
__device__ __nv_bfloat16 g_w1t_hi[H_ * H_];
__device__ __nv_bfloat16 g_w1t_lo[H_ * H_];

// ---------------- f32x2 helpers ----------------
__device__ __forceinline__ u64_t bcast2(float x) {
    u64_t r; asm("mov.b64 %0, {%1,%2};" : "=l"(r) : "f"(x), "f"(x)); return r;
}
__device__ __forceinline__ u64_t lo2(const float4& v) {
    u64_t r; asm("mov.b64 %0, {%1,%2};" : "=l"(r) : "f"(v.x), "f"(v.y)); return r;
}
__device__ __forceinline__ u64_t hi2(const float4& v) {
    u64_t r; asm("mov.b64 %0, {%1,%2};" : "=l"(r) : "f"(v.z), "f"(v.w)); return r;
}
__device__ __forceinline__ void fma2(u64_t& d, u64_t a, u64_t b) {
    asm("fma.rn.f32x2 %0, %1, %2, %0;" : "+l"(d) : "l"(a), "l"(b));
}
__device__ __forceinline__ float2 unpack2(u64_t v) {
    float2 r; asm("mov.b64 {%0,%1}, %2;" : "=f"(r.x), "=f"(r.y) : "l"(v)); return r;
}

// ---------------- FMA-only activations (no MUFU) ----------------
__device__ __forceinline__ float frcp_fast(float d) {
    float r = __uint_as_float(0x7EF311C3u - __float_as_uint(d));
    r = r * (2.0f - d * r);
    r = r * (2.0f - d * r);
    return r;
}
__device__ __forceinline__ float tanh_fast(float x) {
    x = fminf(7.90531f, fmaxf(-7.90531f, x));
    float x2 = x * x;
    float p = -2.76076847742355e-16f;
    p = fmaf(p, x2, 2.00018790482477e-13f);
    p = fmaf(p, x2, -8.60467152213735e-11f);
    p = fmaf(p, x2, 5.12229709037114e-08f);
    p = fmaf(p, x2, 1.48572235717979e-05f);
    p = fmaf(p, x2, 6.37261928875436e-04f);
    p = fmaf(p, x2, 4.89352455891786e-03f);
    p = p * x;
    float q = 1.19825839466702e-06f;
    q = fmaf(q, x2, 1.18534705686654e-04f);
    q = fmaf(q, x2, 2.26843463243900e-03f);
    q = fmaf(q, x2, 4.89352518554385e-03f);
    return p * frcp_fast(q);
}
__device__ __forceinline__ float sigmoid_fast(float x) {
    return 0.5f + 0.5f * tanh_fast(0.5f * x);
}

// ---------------- mma.sync helpers ----------------
__device__ __forceinline__ uint32_t smem_u32(const void* p) {
    uint32_t a;
    asm("{ .reg .u64 t; cvta.to.shared.u64 t, %1; cvt.u32.u64 %0, t; }" : "=r"(a) : "l"(p));
    return a;
}
__device__ __forceinline__ void ldm_x4(uint32_t& r0, uint32_t& r1, uint32_t& r2, uint32_t& r3,
                                       uint32_t addr) {
    asm volatile("ldmatrix.sync.aligned.m8n8.x4.shared.b16 {%0,%1,%2,%3}, [%4];"
                 : "=r"(r0), "=r"(r1), "=r"(r2), "=r"(r3) : "r"(addr));
}
__device__ __forceinline__ void ldm_x2(uint32_t& r0, uint32_t& r1, uint32_t addr) {
    asm volatile("ldmatrix.sync.aligned.m8n8.x2.shared.b16 {%0,%1}, [%2];"
                 : "=r"(r0), "=r"(r1) : "r"(addr));
}
__device__ __forceinline__ void mma_bf16(float* c, const uint32_t* a, const uint32_t* b) {
    asm volatile("mma.sync.aligned.m16n8k16.row.col.f32.bf16.bf16.f32 "
                 "{%0,%1,%2,%3}, {%4,%5,%6,%7}, {%8,%9}, {%0,%1,%2,%3};"
                 : "+f"(c[0]), "+f"(c[1]), "+f"(c[2]), "+f"(c[3])
                 : "r"(a[0]), "r"(a[1]), "r"(a[2]), "r"(a[3]), "r"(b[0]), "r"(b[1]));
}
__device__ __forceinline__ void cp16(uint32_t dst, const void* src) {
    asm volatile("cp.async.ca.shared.global [%0], [%1], 16;" :: "r"(dst), "l"(src));
}
__device__ __forceinline__ void cp_commit() {
    asm volatile("cp.async.commit_group;" ::: "memory");
}
template <int NW>
__device__ __forceinline__ void cp_wait() {
    asm volatile("cp.async.wait_group %0;" :: "n"(NW) : "memory");
}
// XOR swizzle for [rows][128] bf16 arrays (256 B/row): byte offset
__device__ __forceinline__ int swz(int row, int col) {
    return row * 256 + ((((col >> 3) ^ (row & 7)) << 4) | ((col & 7) << 1));
}

// ---------------- adjacency normalization ----------------
__global__ void adj_rowsum_k(const float* __restrict__ adj, float* __restrict__ dis) {
    int i = threadIdx.x;
    float s = 1.0f;
    for (int j = 0; j < N_; j++) s += adj[i * N_ + j];
    dis[i] = (s > 0.0f) ? rsqrtf(s) : 0.0f;
}
__global__ void adj_norm_k(const float* __restrict__ adj, const float* __restrict__ dis,
                           float* __restrict__ out,
                           __nv_bfloat16* __restrict__ ohi, __nv_bfloat16* __restrict__ olo) {
    int j = blockIdx.x * blockDim.x + threadIdx.x;
    int i = blockIdx.y;
    float a = adj[i * N_ + j] + (i == j ? 1.0f : 0.0f);
    float v = dis[i] * a * dis[j];
    out[i * N_ + j] = v;
    __nv_bfloat16 h = __float2bfloat16(v);
    ohi[i * N_ + j] = h;
    olo[i * N_ + j] = __float2bfloat16(v - __bfloat162float(h));
}

// ---------------- elementwise fp32 -> bf16 hi/lo split ----------------
__global__ void split_k(const float* __restrict__ src, __nv_bfloat16* __restrict__ hi,
                        __nv_bfloat16* __restrict__ lo, int n) {
    int i = blockIdx.x * blockDim.x + threadIdx.x;
    if (i >= n) return;
    float v = src[i];
    __nv_bfloat16 h = __float2bfloat16(v);
    hi[i] = h;
    lo[i] = __float2bfloat16(v - __bfloat162float(h));
}

// ---------------- transposed split of a [K x N] matrix -> [N x K] hi/lo ----------------
__global__ void wtr_split_k(const float* __restrict__ w,
                            __nv_bfloat16* __restrict__ hi, __nv_bfloat16* __restrict__ lo) {
    for (int i = threadIdx.x; i < H_ * H_; i += 256) {
        int n = i >> 7, k = i & 127;
        float v = w[k * H_ + n];
        __nv_bfloat16 h = __float2bfloat16(v);
        hi[i] = h;
        lo[i] = __float2bfloat16(v - __bfloat162float(h));
    }
}

// ---------------- transpose + split: src[b][node][c] -> dst[b][c][node] bf16 hi/lo ----------------
template <bool MASK>
__global__ void transpose_split_k(const float* __restrict__ src,
                                  __nv_bfloat16* __restrict__ hi, __nv_bfloat16* __restrict__ lo,
                                  int cols) {
    __shared__ float tile[32][33];
    const int b = blockIdx.z;
    const long long cBase = (long long)blockIdx.x * 32;
    const long long nBase = (long long)blockIdx.y * 32;
    const float* s = src + (long long)b * N_ * cols;
    #pragma unroll
    for (int i = threadIdx.y; i < 32; i += 8) {
        float v = s[(nBase + i) * cols + cBase + threadIdx.x];
        if (MASK && v == -1.0f) v = 0.0f;
        tile[i][threadIdx.x] = v;
    }
    __syncthreads();
    const long long ob = (long long)b * cols * N_;
    #pragma unroll
    for (int i = threadIdx.y; i < 32; i += 8) {
        float v = tile[threadIdx.x][i];
        __nv_bfloat16 h = __float2bfloat16(v);
        long long o = ob + (cBase + i) * N_ + nBase + threadIdx.x;
        hi[o] = h;
        lo[o] = __float2bfloat16(v - __bfloat162float(h));
    }
}

// ---------------- tiled fp32 GEMM with FFMA2 (SIMT; step 3 and FC) ----------------
// SPLITO: write relu(D+bias) as bf16 hi/lo planes instead of fp32.
template <int BM, int BN, int BK, int TM, int TN, bool RELU, bool BIAS, bool SPLITO>
__global__ void __launch_bounds__((BM / TM) * (BN / TN))
gemm_k(const float* __restrict__ A, const float* __restrict__ B,
       const float* __restrict__ bias, float* __restrict__ C,
       __nv_bfloat16* __restrict__ Chi, __nv_bfloat16* __restrict__ Clo,
       int M, int N, int K, int bias_mod) {
    constexpr int THREADS = (BM / TM) * (BN / TN);
    constexpr int MCH = TM / 4, NCH = TN / 4;
    constexpr int RS = BM / MCH, CS = BN / NCH;

    __shared__ float As[BK][BM + 4];
    __shared__ float Bs[BK][BN + 4];

    const int tid   = threadIdx.x;
    const int tcols = BN / TN;
    const int trow  = tid / tcols;
    const int tcol  = tid % tcols;
    const long long row0 = (long long)blockIdx.y * BM;
    const int col0 = blockIdx.x * BN;

    u64_t acc[TM][TN / 2];
    #pragma unroll
    for (int m = 0; m < TM; m++)
        #pragma unroll
        for (int p = 0; p < TN / 2; p++) acc[m][p] = 0ULL;

    for (int k0 = 0; k0 < K; k0 += BK) {
        #pragma unroll
        for (int i = tid; i < BM * BK / 4; i += THREADS) {
            int r = i / (BK / 4), kk = (i % (BK / 4)) * 4;
            float4 v = *(const float4*)&A[(row0 + r) * K + k0 + kk];
            As[kk + 0][r] = v.x; As[kk + 1][r] = v.y;
            As[kk + 2][r] = v.z; As[kk + 3][r] = v.w;
        }
        #pragma unroll
        for (int i = tid; i < BK * BN / 4; i += THREADS) {
            int r = i / (BN / 4), c = (i % (BN / 4)) * 4;
            float4 v = *(const float4*)&B[(long long)(k0 + r) * N + col0 + c];
            *(float4*)&Bs[r][c] = v;
        }
        __syncthreads();

        #pragma unroll 4
        for (int k = 0; k < BK; k++) {
            u64_t av[TM];
            #pragma unroll
            for (int i = 0; i < MCH; i++) {
                float4 a = *(const float4*)&As[k][i * RS + trow * 4];
                av[i * 4 + 0] = bcast2(a.x); av[i * 4 + 1] = bcast2(a.y);
                av[i * 4 + 2] = bcast2(a.z); av[i * 4 + 3] = bcast2(a.w);
            }
            u64_t bp[TN / 2];
            #pragma unroll
            for (int j = 0; j < NCH; j++) {
                float4 b = *(const float4*)&Bs[k][j * CS + tcol * 4];
                bp[j * 2 + 0] = lo2(b);
                bp[j * 2 + 1] = hi2(b);
            }
            #pragma unroll
            for (int m = 0; m < TM; m++)
                #pragma unroll
                for (int p = 0; p < TN / 2; p++)
                    fma2(acc[m][p], av[m], bp[p]);
        }
        __syncthreads();
    }

    #pragma unroll
    for (int i = 0; i < MCH; i++) {
        #pragma unroll
        for (int mm = 0; mm < 4; mm++) {
            long long row = row0 + i * RS + trow * 4 + mm;
            int m = i * 4 + mm;
            #pragma unroll
            for (int j = 0; j < NCH; j++) {
                int col = col0 + j * CS + tcol * 4;
                float2 lo = unpack2(acc[m][j * 2]);
                float2 hi = unpack2(acc[m][j * 2 + 1]);
                float4 v = make_float4(lo.x, lo.y, hi.x, hi.y);
                if (BIAS) {
                    int cb = col % bias_mod;
                    v.x += bias[cb]; v.y += bias[cb + 1];
                    v.z += bias[cb + 2]; v.w += bias[cb + 3];
                }
                if (RELU) {
                    v.x = fmaxf(v.x, 0.f); v.y = fmaxf(v.y, 0.f);
                    v.z = fmaxf(v.z, 0.f); v.w = fmaxf(v.w, 0.f);
                }
                if (SPLITO) {
                    __nv_bfloat16 h0 = __float2bfloat16(v.x);
                    __nv_bfloat16 h1 = __float2bfloat16(v.y);
                    __nv_bfloat16 h2 = __float2bfloat16(v.z);
                    __nv_bfloat16 h3 = __float2bfloat16(v.w);
                    __nv_bfloat162 hv0; hv0.x = h0; hv0.y = h1;
                    __nv_bfloat162 hv1; hv1.x = h2; hv1.y = h3;
                    __nv_bfloat162 lv0, lv1;
                    lv0.x = __float2bfloat16(v.x - __bfloat162float(h0));
                    lv0.y = __float2bfloat16(v.y - __bfloat162float(h1));
                    lv1.x = __float2bfloat16(v.z - __bfloat162float(h2));
                    lv1.y = __float2bfloat16(v.w - __bfloat162float(h3));
                    long long o = row * N + col;
                    *(__nv_bfloat162*)(Chi + o) = hv0;
                    *(__nv_bfloat162*)(Chi + o + 2) = hv1;
                    *(__nv_bfloat162*)(Clo + o) = lv0;
                    *(__nv_bfloat162*)(Clo + o + 2) = lv1;
                } else {
                    *(float4*)&C[row * N + col] = v;
                }
            }
        }
    }
}

// ---------------- split-bf16 tensor-core GEMM (mma.sync, cp.async 2-stage; R13 body) ----------------
constexpr int MMA_ARR  = 128 * 40;
constexpr int MMA_STAGE = 4 * MMA_ARR;
constexpr int MMA_SMEM = 2 * MMA_STAGE * 2;        // 81920 bytes

template <bool SPLIT_OUT, bool BIAS>
__global__ void __launch_bounds__(256)
mma_gemm_k(const __nv_bfloat16* __restrict__ Ahi, const __nv_bfloat16* __restrict__ Alo,
           long long lda,
           const __nv_bfloat16* __restrict__ Bhi, const __nv_bfloat16* __restrict__ Blo,
           long long ldb, long long bzRows,
           const float* __restrict__ bias, int bias_mod,
           float* __restrict__ Dout,
           __nv_bfloat16* __restrict__ DhiOut, __nv_bfloat16* __restrict__ DloOut,
           long long ldd, long long dz, int K) {
    extern __shared__ __align__(16) __nv_bfloat16 smem[];

    const int tid = threadIdx.x, wid = tid >> 5, lane = tid & 31;
    const int wm = wid >> 1, wn = wid & 1;
    const long long z = blockIdx.z;
    const long long aRow0 = (long long)blockIdx.y * 128;
    const long long bRow0 = (long long)blockIdx.x * 128 + z * bzRows;

    const __nv_bfloat16* srcs[4] = {Ahi + aRow0 * lda, Alo + aRow0 * lda,
                                    Bhi + bRow0 * ldb, Blo + bRow0 * ldb};
    const long long lds[4] = {lda, lda, ldb, ldb};

    const int e0 = tid, e1 = tid + 256;
    const int r0c = e0 >> 2, q0c = e0 & 3;
    const int r1c = e1 >> 2, q1c = e1 & 3;

    auto load_stage = [&](int stage, int kc) {
        #pragma unroll
        for (int arr = 0; arr < 4; arr++) {
            __nv_bfloat16* dst = smem + stage * MMA_STAGE + arr * MMA_ARR;
            cp16(smem_u32(dst + r0c * 40 + q0c * 8),
                 srcs[arr] + (long long)r0c * lds[arr] + kc + q0c * 8);
            cp16(smem_u32(dst + r1c * 40 + q1c * 8),
                 srcs[arr] + (long long)r1c * lds[arr] + kc + q1c * 8);
        }
        cp_commit();
    };

    float acc[2][8][4];
    #pragma unroll
    for (int mf = 0; mf < 2; mf++)
        #pragma unroll
        for (int nf = 0; nf < 8; nf++)
            #pragma unroll
            for (int q = 0; q < 4; q++) acc[mf][nf][q] = 0.0f;

    const int a_r  = lane & 15;
    const int a_c8 = (lane >> 4) << 3;
    const int b_r  = lane & 7;
    const int b_c8 = ((lane >> 3) & 1) << 3;

    const int nk = K >> 5;
    load_stage(0, 0);

    for (int i = 0; i < nk; i++) {
        const int stage = i & 1;
        if (i + 1 < nk) {
            load_stage(stage ^ 1, (i + 1) << 5);
            cp_wait<1>();
        } else {
            cp_wait<0>();
        }
        __syncthreads();

        const __nv_bfloat16* sAhi = smem + stage * MMA_STAGE + 0 * MMA_ARR;
        const __nv_bfloat16* sAlo = smem + stage * MMA_STAGE + 1 * MMA_ARR;
        const __nv_bfloat16* sBhi = smem + stage * MMA_STAGE + 2 * MMA_ARR;
        const __nv_bfloat16* sBlo = smem + stage * MMA_STAGE + 3 * MMA_ARR;

        #pragma unroll
        for (int ks = 0; ks < 2; ks++) {
            const int kk = ks * 16;
            uint32_t ahi[2][4], alo[2][4];
            #pragma unroll
            for (int mf = 0; mf < 2; mf++) {
                int row = wm * 32 + mf * 16 + a_r;
                ldm_x4(ahi[mf][0], ahi[mf][1], ahi[mf][2], ahi[mf][3],
                       smem_u32(sAhi + row * 40 + kk + a_c8));
                ldm_x4(alo[mf][0], alo[mf][1], alo[mf][2], alo[mf][3],
                       smem_u32(sAlo + row * 40 + kk + a_c8));
            }
            #pragma unroll
            for (int nf = 0; nf < 8; nf++) {
                int n = wn * 64 + nf * 8 + b_r;
                uint32_t bhi[2], blo[2];
                ldm_x2(bhi[0], bhi[1], smem_u32(sBhi + n * 40 + kk + b_c8));
                ldm_x2(blo[0], blo[1], smem_u32(sBlo + n * 40 + kk + b_c8));
                #pragma unroll
                for (int mf = 0; mf < 2; mf++) {
                    mma_bf16(acc[mf][nf], ahi[mf], bhi);
                    mma_bf16(acc[mf][nf], ahi[mf], blo);
                    mma_bf16(acc[mf][nf], alo[mf], bhi);
                }
            }
        }
        __syncthreads();
    }

    const int colBlk = blockIdx.x * 128;
    #pragma unroll
    for (int mf = 0; mf < 2; mf++) {
        #pragma unroll
        for (int nf = 0; nf < 8; nf++) {
            int col = colBlk + wn * 64 + nf * 8 + (lane & 3) * 2;
            float bb0 = 0.f, bb1 = 0.f;
            if (BIAS) {
                int cb = col % bias_mod;
                bb0 = bias[cb]; bb1 = bias[cb + 1];
            }
            long long r0 = aRow0 + wm * 32 + mf * 16 + (lane >> 2);
            #pragma unroll
            for (int h = 0; h < 2; h++) {
                long long row = r0 + h * 8;
                float v0 = acc[mf][nf][h * 2 + 0] + bb0;
                float v1 = acc[mf][nf][h * 2 + 1] + bb1;
                long long o = z * dz + row * ldd + col;
                if (SPLIT_OUT) {
                    v0 = fmaxf(v0, 0.0f); v1 = fmaxf(v1, 0.0f);
                    __nv_bfloat16 h0 = __float2bfloat16(v0);
                    __nv_bfloat16 h1 = __float2bfloat16(v1);
                    __nv_bfloat162 hv; hv.x = h0; hv.y = h1;
                    __nv_bfloat162 lv;
                    lv.x = __float2bfloat16(v0 - __bfloat162float(h0));
                    lv.y = __float2bfloat16(v1 - __bfloat162float(h1));
                    *(__nv_bfloat162*)(DhiOut + o) = hv;
                    *(__nv_bfloat162*)(DloOut + o) = lv;
                } else {
                    float2 fv; fv.x = v0; fv.y = v1;
                    *(float2*)(Dout + o) = fv;
                }
            }
        }
    }
}

// ---------------- fused persistent GRU with tensor-core recurrence (R13 body) ----------------
constexpr int GRU_SMEM = 229376;

__global__ void __launch_bounds__(256, 1)
gru_mma_k(const float* __restrict__ gi, const float* __restrict__ w_hh,
          const float* __restrict__ b_hh, float* __restrict__ out) {
    extern __shared__ __align__(16) char gsm[];
    char* whh_hi = gsm;
    char* whh_lo = gsm + 98304;
    char* h_hi   = gsm + 196608;
    char* h_lo   = gsm + 212992;

    const int tid = threadIdx.x, wid = tid >> 5, lane = tid & 31;
    const int wm = wid >> 2, wn = wid & 3;
    const long long bn0 = (long long)blockIdx.x * 64;

    for (int i = tid; i < 384 * 128; i += 256) {
        int n = i >> 7, c = i & 127;
        float v = w_hh[i];
        __nv_bfloat16 hh = __float2bfloat16(v);
        int off = swz(n, c);
        *(__nv_bfloat16*)(whh_hi + off) = hh;
        *(__nv_bfloat16*)(whh_lo + off) = __float2bfloat16(v - __bfloat162float(hh));
    }
    for (int i = tid * 4; i < 16384; i += 1024) {
        *(uint32_t*)(h_hi + i) = 0;
        *(uint32_t*)(h_lo + i) = 0;
    }

    float bh[3][4][2];
    #pragma unroll
    for (int g = 0; g < 3; g++)
        #pragma unroll
        for (int nf = 0; nf < 4; nf++) {
            int c = g * 128 + wn * 32 + nf * 8 + (lane & 3) * 2;
            bh[g][nf][0] = b_hh[c];
            bh[g][nf][1] = b_hh[c + 1];
        }

    float hreg[2][4][2][2];
    #pragma unroll
    for (int mf = 0; mf < 2; mf++)
        #pragma unroll
        for (int nf = 0; nf < 4; nf++) {
            hreg[mf][nf][0][0] = 0.f; hreg[mf][nf][0][1] = 0.f;
            hreg[mf][nf][1][0] = 0.f; hreg[mf][nf][1][1] = 0.f;
        }
    __syncthreads();

    const int a_r = lane & 15, a_c8 = (lane >> 4) << 3;
    const int b_g = lane >> 3, b_ln = lane & 7;
    const int b_rowadd = ((b_g >> 1) << 3) + b_ln;
    const int b_kadd = (b_g & 1) << 3;

    for (int t = 0; t < T_; t++) {
        float acc[2][3][4][4];
        #pragma unroll
        for (int mf = 0; mf < 2; mf++)
            #pragma unroll
            for (int g = 0; g < 3; g++)
                #pragma unroll
                for (int nf = 0; nf < 4; nf++) {
                    acc[mf][g][nf][0] = 0.f; acc[mf][g][nf][1] = 0.f;
                    acc[mf][g][nf][2] = 0.f; acc[mf][g][nf][3] = 0.f;
                }

        #pragma unroll 1
        for (int ks = 0; ks < 8; ks++) {
            const int kk = ks * 16;
            uint32_t ahi[2][4], alo[2][4];
            #pragma unroll
            for (int mf = 0; mf < 2; mf++) {
                int row = wm * 32 + mf * 16 + a_r;
                ldm_x4(ahi[mf][0], ahi[mf][1], ahi[mf][2], ahi[mf][3],
                       smem_u32(h_hi + swz(row, kk + a_c8)));
                ldm_x4(alo[mf][0], alo[mf][1], alo[mf][2], alo[mf][3],
                       smem_u32(h_lo + swz(row, kk + a_c8)));
            }
            #pragma unroll
            for (int g = 0; g < 3; g++) {
                #pragma unroll
                for (int p = 0; p < 2; p++) {
                    int rowb = g * 128 + wn * 32 + p * 16 + b_rowadd;
                    int kcol = kk + b_kadd;
                    uint32_t bhr[4], blr[4];
                    ldm_x4(bhr[0], bhr[1], bhr[2], bhr[3],
                           smem_u32(whh_hi + swz(rowb, kcol)));
                    ldm_x4(blr[0], blr[1], blr[2], blr[3],
                           smem_u32(whh_lo + swz(rowb, kcol)));
                    #pragma unroll
                    for (int q = 0; q < 2; q++) {
                        int nf = p * 2 + q;
                        uint32_t bh2[2] = {bhr[q * 2], bhr[q * 2 + 1]};
                        uint32_t bl2[2] = {blr[q * 2], blr[q * 2 + 1]};
                        #pragma unroll
                        for (int mf = 0; mf < 2; mf++) {
                            mma_bf16(acc[mf][g][nf], ahi[mf], bh2);
                            mma_bf16(acc[mf][g][nf], ahi[mf], bl2);
                            mma_bf16(acc[mf][g][nf], alo[mf], bh2);
                        }
                    }
                }
            }
        }
        __syncthreads();

        #pragma unroll
        for (int mf = 0; mf < 2; mf++) {
            #pragma unroll
            for (int nf = 0; nf < 4; nf++) {
                #pragma unroll
                for (int hh = 0; hh < 2; hh++) {
                    int m = wm * 32 + mf * 16 + (lane >> 2) + hh * 8;
                    long long rg = bn0 + m;
                    int c = wn * 32 + nf * 8 + (lane & 3) * 2;
                    const float* gp = gi + (rg * T_ + t) * 384 + c;
                    float2 xr = *(const float2*)gp;
                    float2 xz = *(const float2*)(gp + 128);
                    float2 xn = *(const float2*)(gp + 256);
                    float rr0 = sigmoid_fast(xr.x + acc[mf][0][nf][hh * 2]     + bh[0][nf][0]);
                    float rr1 = sigmoid_fast(xr.y + acc[mf][0][nf][hh * 2 + 1] + bh[0][nf][1]);
                    float zz0 = sigmoid_fast(xz.x + acc[mf][1][nf][hh * 2]     + bh[1][nf][0]);
                    float zz1 = sigmoid_fast(xz.y + acc[mf][1][nf][hh * 2 + 1] + bh[1][nf][1]);
                    float nn0 = tanh_fast(xn.x + rr0 * (acc[mf][2][nf][hh * 2]     + bh[2][nf][0]));
                    float nn1 = tanh_fast(xn.y + rr1 * (acc[mf][2][nf][hh * 2 + 1] + bh[2][nf][1]));
                    float hp0 = hreg[mf][nf][hh][0], hp1 = hreg[mf][nf][hh][1];
                    float h0 = fmaf(zz0, hp0 - nn0, nn0);
                    float h1 = fmaf(zz1, hp1 - nn1, nn1);
                    hreg[mf][nf][hh][0] = h0; hreg[mf][nf][hh][1] = h1;

                    float2 o; o.x = h0; o.y = h1;
                    *(float2*)(out + (rg * T_ + t) * 128 + c) = o;

                    __nv_bfloat16 c0 = __float2bfloat16(h0);
                    __nv_bfloat16 c1 = __float2bfloat16(h1);
                    __nv_bfloat162 hv; hv.x = c0; hv.y = c1;
                    __nv_bfloat162 lv;
                    lv.x = __float2bfloat16(h0 - __bfloat162float(c0));
                    lv.y = __float2bfloat16(h1 - __bfloat162float(c1));
                    int off = swz(m, c);
                    *(__nv_bfloat162*)(h_hi + off) = hv;
                    *(__nv_bfloat162*)(h_lo + off) = lv;
                }
            }
        }
        __syncthreads();
    }
}

// ---------------- launch ----------------
extern "C" void kernel_launch(void* const* d_in, const int* in_sizes, int n_in,
                              void* d_out, int out_size) {
    const float* x     = (const float*)d_in[0];
    const float* adj   = (const float*)d_in[1];
    const float* gc_w0 = (const float*)d_in[2];
    const float* gc_b0 = (const float*)d_in[3];
    const float* gc_w1 = (const float*)d_in[4];
    const float* gc_b1 = (const float*)d_in[5];
    const float* w_ih  = (const float*)d_in[6];
    const float* w_hh  = (const float*)d_in[7];
    const float* b_ih  = (const float*)d_in[8];
    const float* b_hh  = (const float*)d_in[9];
    const float* w_fc  = (const float*)d_in[10];
    const float* b_fc  = (const float*)d_in[11];
    float* out = (float*)d_out;

    unsigned char* pool;
    float *adjn, *dis;
    __nv_bfloat16 *adjn_hi, *adjn_lo, *wih_hi, *wih_lo, *w1t_hi, *w1t_lo;
    cudaGetSymbolAddress((void**)&pool,    g_pool);
    cudaGetSymbolAddress((void**)&adjn,    g_adjn);
    cudaGetSymbolAddress((void**)&adjn_hi, g_adjn_hi);
    cudaGetSymbolAddress((void**)&adjn_lo, g_adjn_lo);
    cudaGetSymbolAddress((void**)&dis,     g_dis);
    cudaGetSymbolAddress((void**)&wih_hi,  g_wih_hi);
    cudaGetSymbolAddress((void**)&wih_lo,  g_wih_lo);
    cudaGetSymbolAddress((void**)&w1t_hi,  g_w1t_hi);
    cudaGetSymbolAddress((void**)&w1t_lo,  g_w1t_lo);

    __nv_bfloat16* xt_hi  = (__nv_bfloat16*)(pool + 0);
    __nv_bfloat16* xt_lo  = (__nv_bfloat16*)(pool + 201326592ULL);
    __nv_bfloat16* s1t_hi = (__nv_bfloat16*)(pool + 0);
    __nv_bfloat16* s1t_lo = (__nv_bfloat16*)(pool + 201326592ULL);
    __nv_bfloat16* h1_hi  = (__nv_bfloat16*)(pool + 402653184ULL);
    __nv_bfloat16* h1_lo  = (__nv_bfloat16*)(pool + 603979776ULL);
    float*         s1     = (float*)(pool + 805306368ULL);   // Y0 then S1
    float*         gi     = (float*)(pool + 0);
    __nv_bfloat16* h2_hi  = (__nv_bfloat16*)(pool + 1207959552ULL);
    __nv_bfloat16* h2_lo  = (__nv_bfloat16*)(pool + 1409286144ULL);
    float*         gru_o  = (float*)(pool + 1207959552ULL);

    const int M = (int)M_TOT;   // 786432

    cudaFuncSetAttribute(mma_gemm_k<true, true>,   cudaFuncAttributeMaxDynamicSharedMemorySize, MMA_SMEM);
    cudaFuncSetAttribute(mma_gemm_k<false, true>,  cudaFuncAttributeMaxDynamicSharedMemorySize, MMA_SMEM);
    cudaFuncSetAttribute(mma_gemm_k<false, false>, cudaFuncAttributeMaxDynamicSharedMemorySize, MMA_SMEM);
    cudaFuncSetAttribute(gru_mma_k, cudaFuncAttributeMaxDynamicSharedMemorySize, GRU_SMEM);

    // 1) adjacency normalization (+ bf16 split), w_ih split, gc_w1 transposed split
    adj_rowsum_k<<<1, N_>>>(adj, dis);
    adj_norm_k<<<dim3(N_ / 256, N_), 256>>>(adj, dis, adjn, adjn_hi, adjn_lo);
    split_k<<<(3 * H_ * H_ + 255) / 256, 256>>>(w_ih, wih_hi, wih_lo, 3 * H_ * H_);
    wtr_split_k<<<1, 256>>>(gc_w1, w1t_hi, w1t_lo);

    // 1b) masked transpose+split of x: [b][node][3072] -> xt [b][3072][node]
    transpose_split_k<true><<<dim3((T_ * FIN_) / 32, N_ / 32, B_), dim3(32, 8)>>>(
        x, xt_hi, xt_lo, T_ * FIN_);

    // 2) Y0 = adjn @ mask(x)  (mma; per batch M=512, N=3072, K=512; fp32 out, no bias)
    mma_gemm_k<false, false><<<dim3((T_ * FIN_) / 128, N_ / 128, B_), 256, MMA_SMEM>>>(
        adjn_hi, adjn_lo, N_,
        xt_hi, xt_lo, N_, (long long)T_ * FIN_,
        nullptr, 1,
        s1, nullptr, nullptr,
        (long long)T_ * FIN_, (long long)N_ * T_ * FIN_, N_);

    // 3) h1 = relu(Y0 @ gc_w0 + b0)  (SIMT, split-bf16 out)
    gemm_k<128, 128, 16, 8, 8, true, true, true>
        <<<dim3(1, M / 128), 256>>>(s1 /*Y0*/, gc_w0, gc_b0, nullptr,
                                    h1_hi, h1_lo, M, H_, FIN_, H_);

    // 4) S1 = h1 @ gc_w1  (mma; M=786432, N=128, K=128; fp32 out, no bias)
    mma_gemm_k<false, false><<<dim3(1, M / 128, 1), 256, MMA_SMEM>>>(
        h1_hi, h1_lo, H_,
        w1t_hi, w1t_lo, H_, 0,
        nullptr, 1,
        s1, nullptr, nullptr,
        H_, 0, H_);

    // 4b) transpose + split: S1 -> S1T bf16 hi/lo
    transpose_split_k<false><<<dim3((T_ * H_) / 32, N_ / 32, B_), dim3(32, 8)>>>(
        s1, s1t_hi, s1t_lo, T_ * H_);

    // 5) h2 = relu(adjn @ S1 + b1)  (mma; split out)
    mma_gemm_k<true, true><<<dim3((T_ * H_) / 128, N_ / 128, B_), 256, MMA_SMEM>>>(
        adjn_hi, adjn_lo, N_,
        s1t_hi, s1t_lo, N_, (long long)T_ * H_,
        gc_b1, H_,
        nullptr, h2_hi, h2_lo,
        (long long)T_ * H_, (long long)N_ * T_ * H_, N_);

    // 6) GI = h2 @ w_ih^T + b_ih  (mma; fp32 out + bias)
    mma_gemm_k<false, true><<<dim3((3 * H_) / 128, M / 128, 1), 256, MMA_SMEM>>>(
        h2_hi, h2_lo, H_,
        wih_hi, wih_lo, H_, 0,
        b_ih, 3 * H_,
        gi, nullptr, nullptr,
        3 * H_, 0, H_);

    // 7) fused GRU recurrence, tensor-core gh
    gru_mma_k<<<BN_TOT / 64, 256, GRU_SMEM>>>(gi, w_hh, b_hh, gru_o);

    // 8) FC: out = gru_out @ w_fc + b_fc  (SIMT)
    gemm_k<128, 32, 16, 8, 4, false, true, false>
        <<<dim3(1, M / 128), 128>>>(gru_o, w_fc, b_fc, out,
                                    nullptr, nullptr, M, FOUT_, H_, FOUT_);
}